// round 14
// baseline (speedup 1.0000x reference)
#include <cuda_runtime.h>
#include <stdint.h>

#define NSAMP 150
#define D_IN  784
#define D_H   512
#define D_OUT 10
#define BATCH 64

// ---------------- device scratch: activations only ----------------
__device__ __align__(16) float g_X [BATCH * D_IN];          // tf32-rounded x
__device__ __align__(16) float g_H1[NSAMP * BATCH * D_H];   // tf32-rounded
__device__ __align__(16) float g_H2[NSAMP * BATCH * D_H];   // tf32-rounded
__device__ __align__(16) float g_H3[NSAMP * BATCH * D_H];   // fp32 (layer3 input)

// ---------------- tf32 helpers ----------------
__device__ __forceinline__ float tf32_round(float a) {
    uint32_t h;
    asm("cvt.rna.tf32.f32 %0, %1;" : "=r"(h) : "f"(a));
    return __uint_as_float(h);
}
__device__ __forceinline__ void mma_tf32(float* c,
                                         uint32_t a0, uint32_t a1, uint32_t a2, uint32_t a3,
                                         uint32_t b0, uint32_t b1) {
    asm("mma.sync.aligned.m16n8k8.row.col.f32.tf32.tf32.f32 "
        "{%0,%1,%2,%3}, {%4,%5,%6,%7}, {%8,%9}, {%0,%1,%2,%3};"
        : "+f"(c[0]), "+f"(c[1]), "+f"(c[2]), "+f"(c[3])
        : "r"(a0), "r"(a1), "r"(a2), "r"(a3), "r"(b0), "r"(b1));
}

// ---------------- threefry2x32 (20 rounds), bit-exact vs jax._src.prng ----------------
// Round adds routed to the FMA pipe via IMAD (runtime 'one' defeats const-folding);
// rotates/xors stay SHF/LOP3 on the alu pipe (R13 showed wide-mul rotates regress).
__device__ __forceinline__ void imad_add(uint32_t& d, uint32_t a, uint32_t one) {
    asm("mad.lo.u32 %0, %1, %2, %0;" : "+r"(d) : "r"(a), "r"(one));
}
__device__ __forceinline__ void tf_round_m(uint32_t& x0, uint32_t& x1, int r, uint32_t one) {
    imad_add(x0, x1, one);                 // x0 += x1   (IMAD, fma pipe)
    x1 = __funnelshift_l(x1, x1, r);       // SHF        (alu pipe)
    x1 ^= x0;                              // LOP3       (alu pipe)
}
__device__ __forceinline__ uint2 threefry2x32_dev(uint32_t k0, uint32_t k1,
                                                  uint32_t x0, uint32_t x1,
                                                  uint32_t one) {
    uint32_t k2 = k0 ^ k1 ^ 0x1BD11BDAu;
    imad_add(x0, k0, one); x1 += k1;
    tf_round_m(x0,x1,13,one); tf_round_m(x0,x1,15,one); tf_round_m(x0,x1,26,one); tf_round_m(x0,x1,6,one);
    imad_add(x0, k1, one); x1 += k2 + 1u;
    tf_round_m(x0,x1,17,one); tf_round_m(x0,x1,29,one); tf_round_m(x0,x1,16,one); tf_round_m(x0,x1,24,one);
    imad_add(x0, k2, one); x1 += k0 + 2u;
    tf_round_m(x0,x1,13,one); tf_round_m(x0,x1,15,one); tf_round_m(x0,x1,26,one); tf_round_m(x0,x1,6,one);
    imad_add(x0, k0, one); x1 += k1 + 3u;
    tf_round_m(x0,x1,17,one); tf_round_m(x0,x1,29,one); tf_round_m(x0,x1,16,one); tf_round_m(x0,x1,24,one);
    imad_add(x0, k1, one); x1 += k2 + 4u;
    tf_round_m(x0,x1,13,one); tf_round_m(x0,x1,15,one); tf_round_m(x0,x1,26,one); tf_round_m(x0,x1,6,one);
    imad_add(x0, k2, one); x1 += k0 + 5u;
    return make_uint2(x0, x1);
}

// ---------------- bits -> N(0,1): fast-math clone of XLA pipeline ----------------
__device__ __forceinline__ float jax_normal_fast(uint32_t bits) {
    const float LO = -0.99999994039535522461f;
    float f = __uint_as_float((bits >> 9) | 0x3f800000u) - 1.0f;
    float x = fmaxf(__fmaf_rn(f, 2.0f, LO), LO);
    float y = x * x;
    float t = 1.0f - y;
    float w = (t == 1.0f) ? y : -__logf(t);
    float p;
    if (w < 5.0f) {
        float ww = w - 2.5f;
        p =                2.81022636e-08f;
        p = __fmaf_rn(p, ww, 3.43273939e-07f);
        p = __fmaf_rn(p, ww, -3.5233877e-06f);
        p = __fmaf_rn(p, ww, -4.39150654e-06f);
        p = __fmaf_rn(p, ww, 0.00021858087f);
        p = __fmaf_rn(p, ww, -0.00125372503f);
        p = __fmaf_rn(p, ww, -0.00417768164f);
        p = __fmaf_rn(p, ww, 0.246640727f);
        p = __fmaf_rn(p, ww, 1.50140941f);
    } else {
        float ww = __fsqrt_rn(w) - 3.0f;
        p =                -0.000200214257f;
        p = __fmaf_rn(p, ww, 0.000100950558f);
        p = __fmaf_rn(p, ww, 0.00134934322f);
        p = __fmaf_rn(p, ww, -0.00367342844f);
        p = __fmaf_rn(p, ww, 0.00573950773f);
        p = __fmaf_rn(p, ww, -0.0076224613f);
        p = __fmaf_rn(p, ww, 0.00943887047f);
        p = __fmaf_rn(p, ww, 1.00167406f);
        p = __fmaf_rn(p, ww, 2.83297682f);
    }
    return 1.4142135623730951f * (p * x);
}

// gen 4 weights at k = kk..kk+3 (row n_glob), tf32-rounded
__device__ __forceinline__ void gen_w4(const float* __restrict__ muRow,
                                       const float* __restrict__ vRow,
                                       int kk, uint32_t eBase,
                                       uint32_t wk0, uint32_t wk1, uint32_t one,
                                       float* w) {
    float4 mv = *(const float4*)(muRow + kk);
    float4 vv = *(const float4*)(vRow  + kk);
    uint32_t e0 = eBase + (uint32_t)kk;
    uint2 r0 = threefry2x32_dev(wk0, wk1, 0u, e0 + 0, one);
    uint2 r1 = threefry2x32_dev(wk0, wk1, 0u, e0 + 1, one);
    uint2 r2 = threefry2x32_dev(wk0, wk1, 0u, e0 + 2, one);
    uint2 r3 = threefry2x32_dev(wk0, wk1, 0u, e0 + 3, one);
    w[0] = tf32_round(__fmaf_rn(__expf(vv.x), jax_normal_fast(r0.x ^ r0.y), mv.x));
    w[1] = tf32_round(__fmaf_rn(__expf(vv.y), jax_normal_fast(r1.x ^ r1.y), mv.y));
    w[2] = tf32_round(__fmaf_rn(__expf(vv.z), jax_normal_fast(r2.x ^ r2.y), mv.z));
    w[3] = tf32_round(__fmaf_rn(__expf(vv.w), jax_normal_fast(r3.x ^ r3.y), mv.w));
}

// gen stage (32 k) directly into smem buffers (no register staging)
__device__ __forceinline__ void gen_stage(
    const float* __restrict__ Ab, const float* __restrict__ muRow,
    const float* __restrict__ vRow, int K, int k0,
    uint32_t eBase, uint32_t wk0, uint32_t wk1, uint32_t one,
    float (*Asb)[68], float (*Bsb)[68], int lr, int lk4)
{
    float4 av0 = *(const float4*)(Ab + (long long)lr * K + k0 + lk4);
    float w[4];
    gen_w4(muRow, vRow, k0 + lk4, eBase, wk0, wk1, one, w);
    Asb[lk4+0][lr] = av0.x; Asb[lk4+1][lr] = av0.y;
    Asb[lk4+2][lr] = av0.z; Asb[lk4+3][lr] = av0.w;
    Bsb[lk4+0][lr] = w[0];  Bsb[lk4+1][lr] = w[1];
    Bsb[lk4+2][lr] = w[2];  Bsb[lk4+3][lr] = w[3];
    if (k0 + 32 <= K) {
        float4 av1 = *(const float4*)(Ab + (long long)lr * K + k0 + 16 + lk4);
        gen_w4(muRow, vRow, k0 + 16 + lk4, eBase, wk0, wk1, one, w);
        Asb[16+lk4+0][lr] = av1.x; Asb[16+lk4+1][lr] = av1.y;
        Asb[16+lk4+2][lr] = av1.z; Asb[16+lk4+3][lr] = av1.w;
        Bsb[16+lk4+0][lr] = w[0];  Bsb[16+lk4+1][lr] = w[1];
        Bsb[16+lk4+2][lr] = w[2];  Bsb[16+lk4+3][lr] = w[3];
    } else {
        Asb[16+lk4+0][lr] = 0.f; Asb[16+lk4+1][lr] = 0.f;
        Asb[16+lk4+2][lr] = 0.f; Asb[16+lk4+3][lr] = 0.f;
        Bsb[16+lk4+0][lr] = 0.f; Bsb[16+lk4+1][lr] = 0.f;
        Bsb[16+lk4+2][lr] = 0.f; Bsb[16+lk4+3][lr] = 0.f;
    }
}

// MMA over one 32-k stage: 4 k8-steps x 4 n8-tiles, 1-term tf32
__device__ __forceinline__ void mma_stage(const float (*Asb)[68], const float (*Bsb)[68],
                                          float acc[4][4], int m0, int n0b,
                                          int ka, int ra)
{
#pragma unroll
    for (int ks = 0; ks < 4; ks++) {
        const int kb = ks * 8;
        uint32_t a0 = __float_as_uint(Asb[kb + ka    ][m0 + ra    ]);
        uint32_t a1 = __float_as_uint(Asb[kb + ka    ][m0 + ra + 8]);
        uint32_t a2 = __float_as_uint(Asb[kb + ka + 4][m0 + ra    ]);
        uint32_t a3 = __float_as_uint(Asb[kb + ka + 4][m0 + ra + 8]);
#pragma unroll
        for (int tj = 0; tj < 4; tj++) {
            uint32_t b0 = __float_as_uint(Bsb[kb + ka    ][n0b + tj * 8 + ra]);
            uint32_t b1 = __float_as_uint(Bsb[kb + ka + 4][n0b + tj * 8 + ra]);
            mma_tf32(acc[tj], a0, a1, a2, a3, b0, b1);
        }
    }
}

// ---------------- tiny pre-kernel: round x to tf32 ----------------
__global__ void round_x(const float* __restrict__ x, float* __restrict__ xr, int n) {
    int i = blockIdx.x * blockDim.x + threadIdx.x;
    if (i < n) xr[i] = tf32_round(x[i]);
}

// ---------------- fused layer: 64x64 tile, 32k stages, 1 barrier/stage, 1-term tf32 -------
// Warp-phase alternation: odd warps run MMA(c) before gen(c+1), even warps the reverse,
// so ALU (gen) and MMA/LDS phases overlap across warps instead of thrashing in lockstep.
__global__ __launch_bounds__(256, 4) void fused_layer(
    const float* __restrict__ A, long long strideA,
    const float* __restrict__ muW, const float* __restrict__ vW,
    const float* __restrict__ mub, const float* __restrict__ vb,
    float* __restrict__ C, int K, int N, int relu, int round_out,
    uint32_t wk0, uint32_t wk1, uint32_t bk0, uint32_t bk1, uint32_t one)
{
    const int s    = blockIdx.y;
    const int nblk = blockIdx.x;
    const int t    = threadIdx.x;      // 256

    __shared__ float As[2][32][68];    // [buf][k][m]  (tf32 values)
    __shared__ float Bs[2][32][68];    // [buf][k][n]  (tf32 values)
    __shared__ float bias_s[64];

    const int lr   = t >> 2;           // 0..63 row (A-row / W-row) producer
    const int lk4  = (t & 3) << 2;     // k offset 0,4,8,12 within 16-k half
    const int lane = t & 31;
    const int wrp  = t >> 5;           // 0..7
    const int m0   = (wrp & 3) * 16;
    const int n0b  = (wrp >> 2) * 32;
    const int ka   = lane & 3;
    const int ra   = lane >> 2;

    const float* Ab     = A + (long long)s * strideA;
    const int    n_glob = nblk * 64 + lr;
    const float* muRow  = muW + (long long)n_glob * K;
    const float* vRow   = vW  + (long long)n_glob * K;
    const uint32_t eBase = ((uint32_t)s * (uint32_t)N + (uint32_t)n_glob) * (uint32_t)K;

    if (t < 64) {
        int nb = nblk * 64 + t;
        uint2 r = threefry2x32_dev(bk0, bk1, 0u, (uint32_t)(s * N + nb), one);
        bias_s[t] = __fmaf_rn(__expf(vb[nb]), jax_normal_fast(r.x ^ r.y), mub[nb]);
    }

    const int nst = (K + 31) >> 5;     // 32-k stages (last half-stage zero-padded)

    // ---- prologue: gen stage 0 straight into buf 0 ----
    gen_stage(Ab, muRow, vRow, K, 0, eBase, wk0, wk1, one, As[0], Bs[0], lr, lk4);

    float acc[4][4];
#pragma unroll
    for (int i = 0; i < 4; i++)
#pragma unroll
        for (int j = 0; j < 4; j++) acc[i][j] = 0.0f;

    // ---- main loop: sync | {gen(c+1) ; MMA(c)} with per-warp phase order ----
    for (int c = 0; c < nst; c++) {
        __syncthreads();
        const int buf = c & 1;
        const bool has_next = (c + 1 < nst);

        if (wrp & 1) {
            // odd warps: consume first, then produce
            mma_stage(As[buf], Bs[buf], acc, m0, n0b, ka, ra);
            if (has_next)
                gen_stage(Ab, muRow, vRow, K, (c + 1) << 5, eBase, wk0, wk1, one,
                          As[buf ^ 1], Bs[buf ^ 1], lr, lk4);
        } else {
            // even warps: produce first, then consume
            if (has_next)
                gen_stage(Ab, muRow, vRow, K, (c + 1) << 5, eBase, wk0, wk1, one,
                          As[buf ^ 1], Bs[buf ^ 1], lr, lk4);
            mma_stage(As[buf], Bs[buf], acc, m0, n0b, ka, ra);
        }
    }

    // ---- epilogue: +bias, relu, optional tf32 round, store ----
    const int row0 = m0 + ra;
    const int row1 = m0 + ra + 8;
#pragma unroll
    for (int tj = 0; tj < 4; tj++) {
        int n = n0b + tj * 8 + 2 * ka;
        float bb0 = bias_s[n], bb1 = bias_s[n + 1];
        float v00 = acc[tj][0] + bb0, v01 = acc[tj][1] + bb1;
        float v10 = acc[tj][2] + bb0, v11 = acc[tj][3] + bb1;
        if (relu) {
            v00 = fmaxf(v00, 0.f); v01 = fmaxf(v01, 0.f);
            v10 = fmaxf(v10, 0.f); v11 = fmaxf(v11, 0.f);
        }
        if (round_out) {
            v00 = tf32_round(v00); v01 = tf32_round(v01);
            v10 = tf32_round(v10); v11 = tf32_round(v11);
        }
        float* p0 = C + ((long long)s * 64 + row0) * N + nblk * 64 + n;
        float* p1 = C + ((long long)s * 64 + row1) * N + nblk * 64 + n;
        *(float2*)p0 = make_float2(v00, v01);
        *(float2*)p1 = make_float2(v10, v11);
    }
}

// ---------------- final layer: 2 blocks per sample, gen partitioned by output-half --------
__global__ __launch_bounds__(256) void layer3_fused(
    const float* __restrict__ H,
    const float* __restrict__ muW, const float* __restrict__ vW,
    const float* __restrict__ mub, const float* __restrict__ vb,
    float* __restrict__ out,
    uint32_t wk0, uint32_t wk1, uint32_t bk0, uint32_t bk1, uint32_t one)
{
    const int s = blockIdx.x;
    const int h = blockIdx.y;
    const int t = threadIdx.x;
    __shared__ float Ws[5 * D_H];
    __shared__ float bsm[5];

#pragma unroll
    for (int i = 0; i < (5 * D_H) / 256; i++) {
        int j = t + 256 * i;
        uint32_t e = (uint32_t)(s * (D_OUT * D_H) + h * (5 * D_H) + j);
        uint2 r = threefry2x32_dev(wk0, wk1, 0u, e, one);
        int jg = h * (5 * D_H) + j;
        Ws[j] = __fmaf_rn(__expf(vW[jg]), jax_normal_fast(r.x ^ r.y), muW[jg]);
    }
    if (t < 5) {
        int og = h * 5 + t;
        uint2 r = threefry2x32_dev(bk0, bk1, 0u, (uint32_t)(s * D_OUT + og), one);
        bsm[t] = __fmaf_rn(__expf(vb[og]), jax_normal_fast(r.x ^ r.y), mub[og]);
    }
    __syncthreads();

    const int w = t >> 5, l = t & 31;
#pragma unroll
    for (int ri = 0; ri < 8; ri++) {
        int b = w * 8 + ri;
        const float* Hb = H + ((long long)s * BATCH + b) * D_H;
        float hh[16];
#pragma unroll
        for (int i = 0; i < 16; i++) hh[i] = Hb[l + 32 * i];
#pragma unroll
        for (int o = 0; o < 5; o++) {
            float acc = 0.0f;
#pragma unroll
            for (int i = 0; i < 16; i++)
                acc = __fmaf_rn(hh[i], Ws[o * D_H + l + 32 * i], acc);
            acc += __shfl_xor_sync(0xffffffffu, acc, 16);
            acc += __shfl_xor_sync(0xffffffffu, acc, 8);
            acc += __shfl_xor_sync(0xffffffffu, acc, 4);
            acc += __shfl_xor_sync(0xffffffffu, acc, 2);
            acc += __shfl_xor_sync(0xffffffffu, acc, 1);
            if (l == 0)
                out[((long long)s * BATCH + b) * D_OUT + h * 5 + o] = acc + bsm[o];
        }
    }
}

// ---------------- host-side threefry (subkey derivation) ----------------
static inline uint32_t h_rotl(uint32_t x, int r) { return (x << r) | (x >> (32 - r)); }
static void tf_host(uint32_t k0, uint32_t k1, uint32_t x0, uint32_t x1,
                    uint32_t* o0, uint32_t* o1) {
    uint32_t k2 = k0 ^ k1 ^ 0x1BD11BDAu;
    x0 += k0; x1 += k1;
    static const int R[2][4] = {{13,15,26,6},{17,29,16,24}};
    const uint32_t ks[3] = {k0, k1, k2};
    for (int i = 0; i < 5; i++) {
        for (int r = 0; r < 4; r++) {
            x0 += x1; x1 = h_rotl(x1, R[i & 1][r]); x1 ^= x0;
        }
        x0 += ks[(i + 1) % 3];
        x1 += ks[(i + 2) % 3] + (uint32_t)(i + 1);
    }
    *o0 = x0; *o1 = x1;
}

extern "C" void kernel_launch(void* const* d_in, const int* in_sizes, int n_in,
                              void* d_out, int out_size) {
    const float* x    = (const float*)d_in[0];
    const float* muW0 = (const float*)d_in[1];
    const float* mub0 = (const float*)d_in[2];
    const float* muW1 = (const float*)d_in[3];
    const float* mub1 = (const float*)d_in[4];
    const float* muW2 = (const float*)d_in[5];
    const float* mub2 = (const float*)d_in[6];
    const float* muW3 = (const float*)d_in[7];
    const float* mub3 = (const float*)d_in[8];
    const float* vW0  = (const float*)d_in[9];
    const float* vb0  = (const float*)d_in[10];
    const float* vW1  = (const float*)d_in[11];
    const float* vb1  = (const float*)d_in[12];
    const float* vW2  = (const float*)d_in[13];
    const float* vb2  = (const float*)d_in[14];
    const float* vW3  = (const float*)d_in[15];
    const float* vb3  = (const float*)d_in[16];
    float* out = (float*)d_out;

    uint32_t kk[8][2];
    for (int i = 0; i < 8; i++) tf_host(0u, 1u, 0u, (uint32_t)i, &kk[i][0], &kk[i][1]);

    float *pX, *pH1, *pH2, *pH3;
    cudaGetSymbolAddress((void**)&pX,  g_X);
    cudaGetSymbolAddress((void**)&pH1, g_H1);
    cudaGetSymbolAddress((void**)&pH2, g_H2);
    cudaGetSymbolAddress((void**)&pH3, g_H3);

    const uint32_t one = 1u;   // runtime constant -> forces IMAD in threefry rounds

    round_x<<<(BATCH * D_IN + 255) / 256, 256>>>(x, pX, BATCH * D_IN);

    fused_layer<<<dim3(D_H/64, NSAMP), 256>>>(pX,  0,
                                              muW0, vW0, mub0, vb0,
                                              pH1, D_IN, D_H, 1, 1,
                                              kk[0][0], kk[0][1], kk[1][0], kk[1][1], one);
    fused_layer<<<dim3(D_H/64, NSAMP), 256>>>(pH1, (long long)BATCH*D_H,
                                              muW1, vW1, mub1, vb1,
                                              pH2, D_H, D_H, 1, 1,
                                              kk[2][0], kk[2][1], kk[3][0], kk[3][1], one);
    fused_layer<<<dim3(D_H/64, NSAMP), 256>>>(pH2, (long long)BATCH*D_H,
                                              muW2, vW2, mub2, vb2,
                                              pH3, D_H, D_H, 1, 0,
                                              kk[4][0], kk[4][1], kk[5][0], kk[5][1], one);
    layer3_fused<<<dim3(NSAMP, 2), 256>>>(pH3, muW3, vW3, mub3, vb3, out,
                                          kk[6][0], kk[6][1], kk[7][0], kk[7][1], one);
}

// round 15
// speedup vs baseline: 1.1553x; 1.1553x over previous
#include <cuda_runtime.h>
#include <stdint.h>

#define NSAMP 150
#define D_IN  784
#define D_H   512
#define D_OUT 10
#define BATCH 64

// ---------------- device scratch ----------------
__device__ __align__(16) float g_X  [BATCH * D_IN];          // tf32-rounded x
__device__ __align__(16) float g_H1 [NSAMP * BATCH * D_H];   // tf32-rounded
__device__ __align__(16) float g_H2 [NSAMP * BATCH * D_H];   // tf32-rounded
__device__ __align__(16) float g_H3 [NSAMP * BATCH * D_H];   // fp32 (layer3 input)
__device__ __align__(16) float g_sd0[D_H * D_IN];            // exp(vW0)
__device__ __align__(16) float g_sd1[D_H * D_H];             // exp(vW1)
__device__ __align__(16) float g_sd2[D_H * D_H];             // exp(vW2)

// ---------------- tf32 helpers ----------------
__device__ __forceinline__ float tf32_round(float a) {
    uint32_t h;
    asm("cvt.rna.tf32.f32 %0, %1;" : "=r"(h) : "f"(a));
    return __uint_as_float(h);
}
__device__ __forceinline__ void mma_tf32(float* c,
                                         uint32_t a0, uint32_t a1, uint32_t a2, uint32_t a3,
                                         uint32_t b0, uint32_t b1) {
    asm("mma.sync.aligned.m16n8k8.row.col.f32.tf32.tf32.f32 "
        "{%0,%1,%2,%3}, {%4,%5,%6,%7}, {%8,%9}, {%0,%1,%2,%3};"
        : "+f"(c[0]), "+f"(c[1]), "+f"(c[2]), "+f"(c[3])
        : "r"(a0), "r"(a1), "r"(a2), "r"(a3), "r"(b0), "r"(b1));
}

// ---------------- threefry2x32 (20 rounds), bit-exact vs jax._src.prng ----------------
// Round adds routed to the FMA pipe via IMAD (runtime 'one' defeats const-folding).
__device__ __forceinline__ void imad_add(uint32_t& d, uint32_t a, uint32_t one) {
    asm("mad.lo.u32 %0, %1, %2, %0;" : "+r"(d) : "r"(a), "r"(one));
}
__device__ __forceinline__ void tf_round_m(uint32_t& x0, uint32_t& x1, int r, uint32_t one) {
    imad_add(x0, x1, one);                 // x0 += x1   (IMAD, fma pipe)
    x1 = __funnelshift_l(x1, x1, r);       // SHF        (alu pipe)
    x1 ^= x0;                              // LOP3       (alu pipe)
}
__device__ __forceinline__ uint2 threefry2x32_dev(uint32_t k0, uint32_t k1,
                                                  uint32_t x0, uint32_t x1,
                                                  uint32_t one) {
    uint32_t k2 = k0 ^ k1 ^ 0x1BD11BDAu;
    imad_add(x0, k0, one); x1 += k1;
    tf_round_m(x0,x1,13,one); tf_round_m(x0,x1,15,one); tf_round_m(x0,x1,26,one); tf_round_m(x0,x1,6,one);
    imad_add(x0, k1, one); x1 += k2 + 1u;
    tf_round_m(x0,x1,17,one); tf_round_m(x0,x1,29,one); tf_round_m(x0,x1,16,one); tf_round_m(x0,x1,24,one);
    imad_add(x0, k2, one); x1 += k0 + 2u;
    tf_round_m(x0,x1,13,one); tf_round_m(x0,x1,15,one); tf_round_m(x0,x1,26,one); tf_round_m(x0,x1,6,one);
    imad_add(x0, k0, one); x1 += k1 + 3u;
    tf_round_m(x0,x1,17,one); tf_round_m(x0,x1,29,one); tf_round_m(x0,x1,16,one); tf_round_m(x0,x1,24,one);
    imad_add(x0, k1, one); x1 += k2 + 4u;
    tf_round_m(x0,x1,13,one); tf_round_m(x0,x1,15,one); tf_round_m(x0,x1,26,one); tf_round_m(x0,x1,6,one);
    imad_add(x0, k2, one); x1 += k0 + 5u;
    return make_uint2(x0, x1);
}

// ---------------- bits -> N(0,1): fast-math clone of XLA pipeline ----------------
__device__ __forceinline__ float jax_normal_fast(uint32_t bits) {
    const float LO = -0.99999994039535522461f;
    float f = __uint_as_float((bits >> 9) | 0x3f800000u) - 1.0f;
    float x = fmaxf(__fmaf_rn(f, 2.0f, LO), LO);
    float y = x * x;
    float t = 1.0f - y;
    float w = (t == 1.0f) ? y : -__logf(t);
    float p;
    if (w < 5.0f) {
        float ww = w - 2.5f;
        p =                2.81022636e-08f;
        p = __fmaf_rn(p, ww, 3.43273939e-07f);
        p = __fmaf_rn(p, ww, -3.5233877e-06f);
        p = __fmaf_rn(p, ww, -4.39150654e-06f);
        p = __fmaf_rn(p, ww, 0.00021858087f);
        p = __fmaf_rn(p, ww, -0.00125372503f);
        p = __fmaf_rn(p, ww, -0.00417768164f);
        p = __fmaf_rn(p, ww, 0.246640727f);
        p = __fmaf_rn(p, ww, 1.50140941f);
    } else {
        float ww = __fsqrt_rn(w) - 3.0f;
        p =                -0.000200214257f;
        p = __fmaf_rn(p, ww, 0.000100950558f);
        p = __fmaf_rn(p, ww, 0.00134934322f);
        p = __fmaf_rn(p, ww, -0.00367342844f);
        p = __fmaf_rn(p, ww, 0.00573950773f);
        p = __fmaf_rn(p, ww, -0.0076224613f);
        p = __fmaf_rn(p, ww, 0.00943887047f);
        p = __fmaf_rn(p, ww, 1.00167406f);
        p = __fmaf_rn(p, ww, 2.83297682f);
    }
    return 1.4142135623730951f * (p * x);
}

// gen 4 weights at k = kk..kk+3 (row n_glob), tf32-rounded. sd = exp(v) precomputed.
__device__ __forceinline__ void gen_w4(const float* __restrict__ muRow,
                                       const float* __restrict__ sdRow,
                                       int kk, uint32_t eBase,
                                       uint32_t wk0, uint32_t wk1, uint32_t one,
                                       float* w) {
    float4 mv = *(const float4*)(muRow + kk);
    float4 sv = *(const float4*)(sdRow + kk);
    uint32_t e0 = eBase + (uint32_t)kk;
    uint2 r0 = threefry2x32_dev(wk0, wk1, 0u, e0 + 0, one);
    uint2 r1 = threefry2x32_dev(wk0, wk1, 0u, e0 + 1, one);
    uint2 r2 = threefry2x32_dev(wk0, wk1, 0u, e0 + 2, one);
    uint2 r3 = threefry2x32_dev(wk0, wk1, 0u, e0 + 3, one);
    w[0] = tf32_round(__fmaf_rn(sv.x, jax_normal_fast(r0.x ^ r0.y), mv.x));
    w[1] = tf32_round(__fmaf_rn(sv.y, jax_normal_fast(r1.x ^ r1.y), mv.y));
    w[2] = tf32_round(__fmaf_rn(sv.z, jax_normal_fast(r2.x ^ r2.y), mv.z));
    w[3] = tf32_round(__fmaf_rn(sv.w, jax_normal_fast(r3.x ^ r3.y), mv.w));
}

// gen stage (32 k) directly into smem buffers (no register staging)
__device__ __forceinline__ void gen_stage(
    const float* __restrict__ Ab, const float* __restrict__ muRow,
    const float* __restrict__ sdRow, int K, int k0,
    uint32_t eBase, uint32_t wk0, uint32_t wk1, uint32_t one,
    float (*Asb)[68], float (*Bsb)[68], int lr, int lk4)
{
    float4 av0 = *(const float4*)(Ab + (long long)lr * K + k0 + lk4);
    float w[4];
    gen_w4(muRow, sdRow, k0 + lk4, eBase, wk0, wk1, one, w);
    Asb[lk4+0][lr] = av0.x; Asb[lk4+1][lr] = av0.y;
    Asb[lk4+2][lr] = av0.z; Asb[lk4+3][lr] = av0.w;
    Bsb[lk4+0][lr] = w[0];  Bsb[lk4+1][lr] = w[1];
    Bsb[lk4+2][lr] = w[2];  Bsb[lk4+3][lr] = w[3];
    if (k0 + 32 <= K) {
        float4 av1 = *(const float4*)(Ab + (long long)lr * K + k0 + 16 + lk4);
        gen_w4(muRow, sdRow, k0 + 16 + lk4, eBase, wk0, wk1, one, w);
        Asb[16+lk4+0][lr] = av1.x; Asb[16+lk4+1][lr] = av1.y;
        Asb[16+lk4+2][lr] = av1.z; Asb[16+lk4+3][lr] = av1.w;
        Bsb[16+lk4+0][lr] = w[0];  Bsb[16+lk4+1][lr] = w[1];
        Bsb[16+lk4+2][lr] = w[2];  Bsb[16+lk4+3][lr] = w[3];
    } else {
        Asb[16+lk4+0][lr] = 0.f; Asb[16+lk4+1][lr] = 0.f;
        Asb[16+lk4+2][lr] = 0.f; Asb[16+lk4+3][lr] = 0.f;
        Bsb[16+lk4+0][lr] = 0.f; Bsb[16+lk4+1][lr] = 0.f;
        Bsb[16+lk4+2][lr] = 0.f; Bsb[16+lk4+3][lr] = 0.f;
    }
}

// ---------------- tiny pre-kernels ----------------
__global__ void round_x(const float* __restrict__ x, float* __restrict__ xr, int n) {
    int i = blockIdx.x * blockDim.x + threadIdx.x;
    if (i < n) xr[i] = tf32_round(x[i]);
}
__global__ void exp_v(const float* __restrict__ v, float* __restrict__ sd, int n) {
    int i = blockIdx.x * blockDim.x + threadIdx.x;
    if (i < n) sd[i] = __expf(v[i]);      // same __expf as gen used -> bit-identical
}

// ---------------- fused layer: 64x64 tile, 32k stages, 1 barrier/stage, 1-term tf32 -------
__global__ __launch_bounds__(256, 4) void fused_layer(
    const float* __restrict__ A, long long strideA,
    const float* __restrict__ muW, const float* __restrict__ sdW,
    const float* __restrict__ mub, const float* __restrict__ vb,
    float* __restrict__ C, int K, int N, int relu, int round_out,
    uint32_t wk0, uint32_t wk1, uint32_t bk0, uint32_t bk1, uint32_t one)
{
    const int s    = blockIdx.y;
    const int nblk = blockIdx.x;
    const int t    = threadIdx.x;      // 256

    __shared__ float As[2][32][68];    // [buf][k][m]  (tf32 values)
    __shared__ float Bs[2][32][68];    // [buf][k][n]  (tf32 values)
    __shared__ float bias_s[64];

    const int lr   = t >> 2;           // 0..63 row (A-row / W-row) producer
    const int lk4  = (t & 3) << 2;     // k offset 0,4,8,12 within 16-k half
    const int lane = t & 31;
    const int wrp  = t >> 5;           // 0..7
    const int m0   = (wrp & 3) * 16;
    const int n0b  = (wrp >> 2) * 32;
    const int ka   = lane & 3;
    const int ra   = lane >> 2;

    const float* Ab     = A + (long long)s * strideA;
    const int    n_glob = nblk * 64 + lr;
    const float* muRow  = muW + (long long)n_glob * K;
    const float* sdRow  = sdW + (long long)n_glob * K;
    const uint32_t eBase = ((uint32_t)s * (uint32_t)N + (uint32_t)n_glob) * (uint32_t)K;

    if (t < 64) {
        int nb = nblk * 64 + t;
        uint2 r = threefry2x32_dev(bk0, bk1, 0u, (uint32_t)(s * N + nb), one);
        bias_s[t] = __fmaf_rn(__expf(vb[nb]), jax_normal_fast(r.x ^ r.y), mub[nb]);
    }

    const int nst = (K + 31) >> 5;     // 32-k stages (last half-stage zero-padded)

    // ---- prologue: gen stage 0 straight into buf 0 ----
    gen_stage(Ab, muRow, sdRow, K, 0, eBase, wk0, wk1, one, As[0], Bs[0], lr, lk4);

    float acc[4][4];
#pragma unroll
    for (int i = 0; i < 4; i++)
#pragma unroll
        for (int j = 0; j < 4; j++) acc[i][j] = 0.0f;

    // ---- main loop: sync | gen(c+1)->buf^1 | MMA(c) from buf ----
    for (int c = 0; c < nst; c++) {
        __syncthreads();
        const int buf = c & 1;

        if (c + 1 < nst) {
            gen_stage(Ab, muRow, sdRow, K, (c + 1) << 5, eBase, wk0, wk1, one,
                      As[buf ^ 1], Bs[buf ^ 1], lr, lk4);
        }

        // MMA over stage c: 4 k8-steps x 4 n8-tiles, 1-term (A & B both tf32)
#pragma unroll
        for (int ks = 0; ks < 4; ks++) {
            const int kb = ks * 8;
            uint32_t a0 = __float_as_uint(As[buf][kb + ka    ][m0 + ra    ]);
            uint32_t a1 = __float_as_uint(As[buf][kb + ka    ][m0 + ra + 8]);
            uint32_t a2 = __float_as_uint(As[buf][kb + ka + 4][m0 + ra    ]);
            uint32_t a3 = __float_as_uint(As[buf][kb + ka + 4][m0 + ra + 8]);
#pragma unroll
            for (int tj = 0; tj < 4; tj++) {
                uint32_t b0 = __float_as_uint(Bs[buf][kb + ka    ][n0b + tj * 8 + ra]);
                uint32_t b1 = __float_as_uint(Bs[buf][kb + ka + 4][n0b + tj * 8 + ra]);
                mma_tf32(acc[tj], a0, a1, a2, a3, b0, b1);
            }
        }
    }

    // ---- epilogue: +bias, relu, optional tf32 round, store ----
    const int row0 = m0 + ra;
    const int row1 = m0 + ra + 8;
#pragma unroll
    for (int tj = 0; tj < 4; tj++) {
        int n = n0b + tj * 8 + 2 * ka;
        float bb0 = bias_s[n], bb1 = bias_s[n + 1];
        float v00 = acc[tj][0] + bb0, v01 = acc[tj][1] + bb1;
        float v10 = acc[tj][2] + bb0, v11 = acc[tj][3] + bb1;
        if (relu) {
            v00 = fmaxf(v00, 0.f); v01 = fmaxf(v01, 0.f);
            v10 = fmaxf(v10, 0.f); v11 = fmaxf(v11, 0.f);
        }
        if (round_out) {
            v00 = tf32_round(v00); v01 = tf32_round(v01);
            v10 = tf32_round(v10); v11 = tf32_round(v11);
        }
        float* p0 = C + ((long long)s * 64 + row0) * N + nblk * 64 + n;
        float* p1 = C + ((long long)s * 64 + row1) * N + nblk * 64 + n;
        *(float2*)p0 = make_float2(v00, v01);
        *(float2*)p1 = make_float2(v10, v11);
    }
}

// ---------------- final layer: 2 blocks per sample, gen partitioned by output-half --------
__global__ __launch_bounds__(256) void layer3_fused(
    const float* __restrict__ H,
    const float* __restrict__ muW, const float* __restrict__ vW,
    const float* __restrict__ mub, const float* __restrict__ vb,
    float* __restrict__ out,
    uint32_t wk0, uint32_t wk1, uint32_t bk0, uint32_t bk1, uint32_t one)
{
    const int s = blockIdx.x;
    const int h = blockIdx.y;
    const int t = threadIdx.x;
    __shared__ float Ws[5 * D_H];
    __shared__ float bsm[5];

#pragma unroll
    for (int i = 0; i < (5 * D_H) / 256; i++) {
        int j = t + 256 * i;
        uint32_t e = (uint32_t)(s * (D_OUT * D_H) + h * (5 * D_H) + j);
        uint2 r = threefry2x32_dev(wk0, wk1, 0u, e, one);
        int jg = h * (5 * D_H) + j;
        Ws[j] = __fmaf_rn(__expf(vW[jg]), jax_normal_fast(r.x ^ r.y), muW[jg]);
    }
    if (t < 5) {
        int og = h * 5 + t;
        uint2 r = threefry2x32_dev(bk0, bk1, 0u, (uint32_t)(s * D_OUT + og), one);
        bsm[t] = __fmaf_rn(__expf(vb[og]), jax_normal_fast(r.x ^ r.y), mub[og]);
    }
    __syncthreads();

    const int w = t >> 5, l = t & 31;
#pragma unroll
    for (int ri = 0; ri < 8; ri++) {
        int b = w * 8 + ri;
        const float* Hb = H + ((long long)s * BATCH + b) * D_H;
        float hh[16];
#pragma unroll
        for (int i = 0; i < 16; i++) hh[i] = Hb[l + 32 * i];
#pragma unroll
        for (int o = 0; o < 5; o++) {
            float acc = 0.0f;
#pragma unroll
            for (int i = 0; i < 16; i++)
                acc = __fmaf_rn(hh[i], Ws[o * D_H + l + 32 * i], acc);
            acc += __shfl_xor_sync(0xffffffffu, acc, 16);
            acc += __shfl_xor_sync(0xffffffffu, acc, 8);
            acc += __shfl_xor_sync(0xffffffffu, acc, 4);
            acc += __shfl_xor_sync(0xffffffffu, acc, 2);
            acc += __shfl_xor_sync(0xffffffffu, acc, 1);
            if (l == 0)
                out[((long long)s * BATCH + b) * D_OUT + h * 5 + o] = acc + bsm[o];
        }
    }
}

// ---------------- host-side threefry (subkey derivation) ----------------
static inline uint32_t h_rotl(uint32_t x, int r) { return (x << r) | (x >> (32 - r)); }
static void tf_host(uint32_t k0, uint32_t k1, uint32_t x0, uint32_t x1,
                    uint32_t* o0, uint32_t* o1) {
    uint32_t k2 = k0 ^ k1 ^ 0x1BD11BDAu;
    x0 += k0; x1 += k1;
    static const int R[2][4] = {{13,15,26,6},{17,29,16,24}};
    const uint32_t ks[3] = {k0, k1, k2};
    for (int i = 0; i < 5; i++) {
        for (int r = 0; r < 4; r++) {
            x0 += x1; x1 = h_rotl(x1, R[i & 1][r]); x1 ^= x0;
        }
        x0 += ks[(i + 1) % 3];
        x1 += ks[(i + 2) % 3] + (uint32_t)(i + 1);
    }
    *o0 = x0; *o1 = x1;
}

extern "C" void kernel_launch(void* const* d_in, const int* in_sizes, int n_in,
                              void* d_out, int out_size) {
    const float* x    = (const float*)d_in[0];
    const float* muW0 = (const float*)d_in[1];
    const float* mub0 = (const float*)d_in[2];
    const float* muW1 = (const float*)d_in[3];
    const float* mub1 = (const float*)d_in[4];
    const float* muW2 = (const float*)d_in[5];
    const float* mub2 = (const float*)d_in[6];
    const float* muW3 = (const float*)d_in[7];
    const float* mub3 = (const float*)d_in[8];
    const float* vW0  = (const float*)d_in[9];
    const float* vb0  = (const float*)d_in[10];
    const float* vW1  = (const float*)d_in[11];
    const float* vb1  = (const float*)d_in[12];
    const float* vW2  = (const float*)d_in[13];
    const float* vb2  = (const float*)d_in[14];
    const float* vW3  = (const float*)d_in[15];
    const float* vb3  = (const float*)d_in[16];
    float* out = (float*)d_out;

    uint32_t kk[8][2];
    for (int i = 0; i < 8; i++) tf_host(0u, 1u, 0u, (uint32_t)i, &kk[i][0], &kk[i][1]);

    float *pX, *pH1, *pH2, *pH3, *pSd0, *pSd1, *pSd2;
    cudaGetSymbolAddress((void**)&pX,   g_X);
    cudaGetSymbolAddress((void**)&pH1,  g_H1);
    cudaGetSymbolAddress((void**)&pH2,  g_H2);
    cudaGetSymbolAddress((void**)&pH3,  g_H3);
    cudaGetSymbolAddress((void**)&pSd0, g_sd0);
    cudaGetSymbolAddress((void**)&pSd1, g_sd1);
    cudaGetSymbolAddress((void**)&pSd2, g_sd2);

    const uint32_t one = 1u;   // runtime constant -> forces IMAD in threefry rounds

    round_x<<<(BATCH * D_IN + 255) / 256, 256>>>(x, pX, BATCH * D_IN);
    exp_v<<<(D_H * D_IN + 255) / 256, 256>>>(vW0, pSd0, D_H * D_IN);
    exp_v<<<(D_H * D_H  + 255) / 256, 256>>>(vW1, pSd1, D_H * D_H);
    exp_v<<<(D_H * D_H  + 255) / 256, 256>>>(vW2, pSd2, D_H * D_H);

    fused_layer<<<dim3(D_H/64, NSAMP), 256>>>(pX,  0,
                                              muW0, pSd0, mub0, vb0,
                                              pH1, D_IN, D_H, 1, 1,
                                              kk[0][0], kk[0][1], kk[1][0], kk[1][1], one);
    fused_layer<<<dim3(D_H/64, NSAMP), 256>>>(pH1, (long long)BATCH*D_H,
                                              muW1, pSd1, mub1, vb1,
                                              pH2, D_H, D_H, 1, 1,
                                              kk[2][0], kk[2][1], kk[3][0], kk[3][1], one);
    fused_layer<<<dim3(D_H/64, NSAMP), 256>>>(pH2, (long long)BATCH*D_H,
                                              muW2, pSd2, mub2, vb2,
                                              pH3, D_H, D_H, 1, 0,
                                              kk[4][0], kk[4][1], kk[5][0], kk[5][1], one);
    layer3_fused<<<dim3(NSAMP, 2), 256>>>(pH3, muW3, vW3, mub3, vb3, out,
                                          kk[6][0], kk[6][1], kk[7][0], kk[7][1], one);
}

// round 16
// speedup vs baseline: 1.2113x; 1.0484x over previous
#include <cuda_runtime.h>
#include <stdint.h>

#define NSAMP 150
#define D_IN  784
#define D_H   512
#define D_OUT 10
#define BATCH 64

// ---------------- device scratch ----------------
__device__ __align__(16) float g_X  [BATCH * D_IN];          // tf32-rounded x
__device__ __align__(16) float g_H1 [NSAMP * BATCH * D_H];   // tf32-rounded
__device__ __align__(16) float g_H2 [NSAMP * BATCH * D_H];   // tf32-rounded
__device__ __align__(16) float g_H3 [NSAMP * BATCH * D_H];   // fp32 (layer3 input)
__device__ __align__(16) float g_sd0[D_H * D_IN];            // exp(vW0)
__device__ __align__(16) float g_sd1[D_H * D_H];             // exp(vW1)
__device__ __align__(16) float g_sd2[D_H * D_H];             // exp(vW2)

// ---------------- tf32 helpers ----------------
__device__ __forceinline__ float tf32_round(float a) {
    uint32_t h;
    asm("cvt.rna.tf32.f32 %0, %1;" : "=r"(h) : "f"(a));
    return __uint_as_float(h);
}
__device__ __forceinline__ void mma_tf32(float* c,
                                         uint32_t a0, uint32_t a1, uint32_t a2, uint32_t a3,
                                         uint32_t b0, uint32_t b1) {
    asm("mma.sync.aligned.m16n8k8.row.col.f32.tf32.tf32.f32 "
        "{%0,%1,%2,%3}, {%4,%5,%6,%7}, {%8,%9}, {%0,%1,%2,%3};"
        : "+f"(c[0]), "+f"(c[1]), "+f"(c[2]), "+f"(c[3])
        : "r"(a0), "r"(a1), "r"(a2), "r"(a3), "r"(b0), "r"(b1));
}

// ---------------- threefry2x32 (20 rounds), bit-exact vs jax._src.prng ----------------
__device__ __forceinline__ void imad_add(uint32_t& d, uint32_t a, uint32_t one) {
    asm("mad.lo.u32 %0, %1, %2, %0;" : "+r"(d) : "r"(a), "r"(one));
}
__device__ __forceinline__ void tf_round_m(uint32_t& x0, uint32_t& x1, int r, uint32_t one) {
    imad_add(x0, x1, one);                 // x0 += x1   (IMAD, fma pipe)
    x1 = __funnelshift_l(x1, x1, r);       // SHF        (alu pipe)
    x1 ^= x0;                              // LOP3       (alu pipe)
}
__device__ __forceinline__ uint2 threefry2x32_dev(uint32_t k0, uint32_t k1,
                                                  uint32_t x0, uint32_t x1,
                                                  uint32_t one) {
    uint32_t k2 = k0 ^ k1 ^ 0x1BD11BDAu;
    imad_add(x0, k0, one); x1 += k1;
    tf_round_m(x0,x1,13,one); tf_round_m(x0,x1,15,one); tf_round_m(x0,x1,26,one); tf_round_m(x0,x1,6,one);
    imad_add(x0, k1, one); x1 += k2 + 1u;
    tf_round_m(x0,x1,17,one); tf_round_m(x0,x1,29,one); tf_round_m(x0,x1,16,one); tf_round_m(x0,x1,24,one);
    imad_add(x0, k2, one); x1 += k0 + 2u;
    tf_round_m(x0,x1,13,one); tf_round_m(x0,x1,15,one); tf_round_m(x0,x1,26,one); tf_round_m(x0,x1,6,one);
    imad_add(x0, k0, one); x1 += k1 + 3u;
    tf_round_m(x0,x1,17,one); tf_round_m(x0,x1,29,one); tf_round_m(x0,x1,16,one); tf_round_m(x0,x1,24,one);
    imad_add(x0, k1, one); x1 += k2 + 4u;
    tf_round_m(x0,x1,13,one); tf_round_m(x0,x1,15,one); tf_round_m(x0,x1,26,one); tf_round_m(x0,x1,6,one);
    imad_add(x0, k2, one); x1 += k0 + 5u;
    return make_uint2(x0, x1);
}

// ---------------- bits -> N(0,1): fast-math clone of XLA pipeline ----------------
// Trims vs XLA: clamp to LO removed (provably a bit-exact no-op: f*2+LO's exact value
// is >= LO and rounding cannot cross the representable LO); the t==1 log1p special
// case removed (affects only |u| < 2^-12-ish lanes by < 1e-7 absolute in eps).
__device__ __forceinline__ float jax_normal_fast(uint32_t bits) {
    const float LO = -0.99999994039535522461f;
    float f = __uint_as_float((bits >> 9) | 0x3f800000u) - 1.0f;
    float x = __fmaf_rn(f, 2.0f, LO);
    float y = x * x;
    float w = -__logf(1.0f - y);
    float p;
    if (w < 5.0f) {
        float ww = w - 2.5f;
        p =                2.81022636e-08f;
        p = __fmaf_rn(p, ww, 3.43273939e-07f);
        p = __fmaf_rn(p, ww, -3.5233877e-06f);
        p = __fmaf_rn(p, ww, -4.39150654e-06f);
        p = __fmaf_rn(p, ww, 0.00021858087f);
        p = __fmaf_rn(p, ww, -0.00125372503f);
        p = __fmaf_rn(p, ww, -0.00417768164f);
        p = __fmaf_rn(p, ww, 0.246640727f);
        p = __fmaf_rn(p, ww, 1.50140941f);
    } else {
        float ww = __fsqrt_rn(w) - 3.0f;
        p =                -0.000200214257f;
        p = __fmaf_rn(p, ww, 0.000100950558f);
        p = __fmaf_rn(p, ww, 0.00134934322f);
        p = __fmaf_rn(p, ww, -0.00367342844f);
        p = __fmaf_rn(p, ww, 0.00573950773f);
        p = __fmaf_rn(p, ww, -0.0076224613f);
        p = __fmaf_rn(p, ww, 0.00943887047f);
        p = __fmaf_rn(p, ww, 1.00167406f);
        p = __fmaf_rn(p, ww, 2.83297682f);
    }
    return 1.4142135623730951f * (p * x);
}

// gen 4 weights at k = kk..kk+3 (row n_glob), tf32-rounded. sd = exp(v) precomputed.
__device__ __forceinline__ void gen_w4(const float* __restrict__ muRow,
                                       const float* __restrict__ sdRow,
                                       int kk, uint32_t eBase,
                                       uint32_t wk0, uint32_t wk1, uint32_t one,
                                       float* w) {
    float4 mv = *(const float4*)(muRow + kk);
    float4 sv = *(const float4*)(sdRow + kk);
    uint32_t e0 = eBase + (uint32_t)kk;
    uint2 r0 = threefry2x32_dev(wk0, wk1, 0u, e0 + 0, one);
    uint2 r1 = threefry2x32_dev(wk0, wk1, 0u, e0 + 1, one);
    uint2 r2 = threefry2x32_dev(wk0, wk1, 0u, e0 + 2, one);
    uint2 r3 = threefry2x32_dev(wk0, wk1, 0u, e0 + 3, one);
    w[0] = tf32_round(__fmaf_rn(sv.x, jax_normal_fast(r0.x ^ r0.y), mv.x));
    w[1] = tf32_round(__fmaf_rn(sv.y, jax_normal_fast(r1.x ^ r1.y), mv.y));
    w[2] = tf32_round(__fmaf_rn(sv.z, jax_normal_fast(r2.x ^ r2.y), mv.z));
    w[3] = tf32_round(__fmaf_rn(sv.w, jax_normal_fast(r3.x ^ r3.y), mv.w));
}

// gen stage (32 k) directly into smem buffers (no register staging)
__device__ __forceinline__ void gen_stage(
    const float* __restrict__ Ab, const float* __restrict__ muRow,
    const float* __restrict__ sdRow, int K, int k0,
    uint32_t eBase, uint32_t wk0, uint32_t wk1, uint32_t one,
    float (*Asb)[68], float (*Bsb)[68], int lr, int lk4)
{
    float4 av0 = *(const float4*)(Ab + (long long)lr * K + k0 + lk4);
    float w[4];
    gen_w4(muRow, sdRow, k0 + lk4, eBase, wk0, wk1, one, w);
    Asb[lk4+0][lr] = av0.x; Asb[lk4+1][lr] = av0.y;
    Asb[lk4+2][lr] = av0.z; Asb[lk4+3][lr] = av0.w;
    Bsb[lk4+0][lr] = w[0];  Bsb[lk4+1][lr] = w[1];
    Bsb[lk4+2][lr] = w[2];  Bsb[lk4+3][lr] = w[3];
    if (k0 + 32 <= K) {
        float4 av1 = *(const float4*)(Ab + (long long)lr * K + k0 + 16 + lk4);
        gen_w4(muRow, sdRow, k0 + 16 + lk4, eBase, wk0, wk1, one, w);
        Asb[16+lk4+0][lr] = av1.x; Asb[16+lk4+1][lr] = av1.y;
        Asb[16+lk4+2][lr] = av1.z; Asb[16+lk4+3][lr] = av1.w;
        Bsb[16+lk4+0][lr] = w[0];  Bsb[16+lk4+1][lr] = w[1];
        Bsb[16+lk4+2][lr] = w[2];  Bsb[16+lk4+3][lr] = w[3];
    } else {
        Asb[16+lk4+0][lr] = 0.f; Asb[16+lk4+1][lr] = 0.f;
        Asb[16+lk4+2][lr] = 0.f; Asb[16+lk4+3][lr] = 0.f;
        Bsb[16+lk4+0][lr] = 0.f; Bsb[16+lk4+1][lr] = 0.f;
        Bsb[16+lk4+2][lr] = 0.f; Bsb[16+lk4+3][lr] = 0.f;
    }
}

// ---------------- merged pre-kernel: round x + exp(vW0/vW1/vW2) in one launch -----------
#define NX   (BATCH * D_IN)                    // 50176
#define NV0  (D_H * D_IN)                      // 401408
#define NV1  (D_H * D_H)                       // 262144
__global__ void prep_all(const float* __restrict__ x,
                         const float* __restrict__ vW0,
                         const float* __restrict__ vW1,
                         const float* __restrict__ vW2,
                         float* __restrict__ xr,
                         float* __restrict__ sd0,
                         float* __restrict__ sd1,
                         float* __restrict__ sd2) {
    int i = blockIdx.x * blockDim.x + threadIdx.x;
    if (i < NX) {
        xr[i] = tf32_round(x[i]);
    }
    if (i < NV0) {
        sd0[i] = __expf(vW0[i]);
    }
    if (i < NV1) {
        sd1[i] = __expf(vW1[i]);
        sd2[i] = __expf(vW2[i]);
    }
}

// ---------------- fused layer: 64x64 tile, 32k stages, 1 barrier/stage, 1-term tf32 -------
__global__ __launch_bounds__(256, 4) void fused_layer(
    const float* __restrict__ A, long long strideA,
    const float* __restrict__ muW, const float* __restrict__ sdW,
    const float* __restrict__ mub, const float* __restrict__ vb,
    float* __restrict__ C, int K, int N, int relu, int round_out,
    uint32_t wk0, uint32_t wk1, uint32_t bk0, uint32_t bk1, uint32_t one)
{
    const int s    = blockIdx.y;
    const int nblk = blockIdx.x;
    const int t    = threadIdx.x;      // 256

    __shared__ float As[2][32][68];    // [buf][k][m]  (tf32 values)
    __shared__ float Bs[2][32][68];    // [buf][k][n]  (tf32 values)
    __shared__ float bias_s[64];

    const int lr   = t >> 2;           // 0..63 row (A-row / W-row) producer
    const int lk4  = (t & 3) << 2;     // k offset 0,4,8,12 within 16-k half
    const int lane = t & 31;
    const int wrp  = t >> 5;           // 0..7
    const int m0   = (wrp & 3) * 16;
    const int n0b  = (wrp >> 2) * 32;
    const int ka   = lane & 3;
    const int ra   = lane >> 2;

    const float* Ab     = A + (long long)s * strideA;
    const int    n_glob = nblk * 64 + lr;
    const float* muRow  = muW + (long long)n_glob * K;
    const float* sdRow  = sdW + (long long)n_glob * K;
    const uint32_t eBase = ((uint32_t)s * (uint32_t)N + (uint32_t)n_glob) * (uint32_t)K;

    if (t < 64) {
        int nb = nblk * 64 + t;
        uint2 r = threefry2x32_dev(bk0, bk1, 0u, (uint32_t)(s * N + nb), one);
        bias_s[t] = __fmaf_rn(__expf(vb[nb]), jax_normal_fast(r.x ^ r.y), mub[nb]);
    }

    const int nst = (K + 31) >> 5;     // 32-k stages (last half-stage zero-padded)

    // ---- prologue: gen stage 0 straight into buf 0 ----
    gen_stage(Ab, muRow, sdRow, K, 0, eBase, wk0, wk1, one, As[0], Bs[0], lr, lk4);

    float acc[4][4];
#pragma unroll
    for (int i = 0; i < 4; i++)
#pragma unroll
        for (int j = 0; j < 4; j++) acc[i][j] = 0.0f;

    // ---- main loop: sync | gen(c+1)->buf^1 | MMA(c) from buf ----
    for (int c = 0; c < nst; c++) {
        __syncthreads();
        const int buf = c & 1;

        if (c + 1 < nst) {
            gen_stage(Ab, muRow, sdRow, K, (c + 1) << 5, eBase, wk0, wk1, one,
                      As[buf ^ 1], Bs[buf ^ 1], lr, lk4);
        }

        // MMA over stage c: 4 k8-steps x 4 n8-tiles, 1-term (A & B both tf32)
#pragma unroll
        for (int ks = 0; ks < 4; ks++) {
            const int kb = ks * 8;
            uint32_t a0 = __float_as_uint(As[buf][kb + ka    ][m0 + ra    ]);
            uint32_t a1 = __float_as_uint(As[buf][kb + ka    ][m0 + ra + 8]);
            uint32_t a2 = __float_as_uint(As[buf][kb + ka + 4][m0 + ra    ]);
            uint32_t a3 = __float_as_uint(As[buf][kb + ka + 4][m0 + ra + 8]);
#pragma unroll
            for (int tj = 0; tj < 4; tj++) {
                uint32_t b0 = __float_as_uint(Bs[buf][kb + ka    ][n0b + tj * 8 + ra]);
                uint32_t b1 = __float_as_uint(Bs[buf][kb + ka + 4][n0b + tj * 8 + ra]);
                mma_tf32(acc[tj], a0, a1, a2, a3, b0, b1);
            }
        }
    }

    // ---- epilogue: +bias, relu, optional tf32 round, store ----
    const int row0 = m0 + ra;
    const int row1 = m0 + ra + 8;
#pragma unroll
    for (int tj = 0; tj < 4; tj++) {
        int n = n0b + tj * 8 + 2 * ka;
        float bb0 = bias_s[n], bb1 = bias_s[n + 1];
        float v00 = acc[tj][0] + bb0, v01 = acc[tj][1] + bb1;
        float v10 = acc[tj][2] + bb0, v11 = acc[tj][3] + bb1;
        if (relu) {
            v00 = fmaxf(v00, 0.f); v01 = fmaxf(v01, 0.f);
            v10 = fmaxf(v10, 0.f); v11 = fmaxf(v11, 0.f);
        }
        if (round_out) {
            v00 = tf32_round(v00); v01 = tf32_round(v01);
            v10 = tf32_round(v10); v11 = tf32_round(v11);
        }
        float* p0 = C + ((long long)s * 64 + row0) * N + nblk * 64 + n;
        float* p1 = C + ((long long)s * 64 + row1) * N + nblk * 64 + n;
        *(float2*)p0 = make_float2(v00, v01);
        *(float2*)p1 = make_float2(v10, v11);
    }
}

// ---------------- final layer: 2 blocks per sample, gen partitioned by output-half --------
__global__ __launch_bounds__(256) void layer3_fused(
    const float* __restrict__ H,
    const float* __restrict__ muW, const float* __restrict__ vW,
    const float* __restrict__ mub, const float* __restrict__ vb,
    float* __restrict__ out,
    uint32_t wk0, uint32_t wk1, uint32_t bk0, uint32_t bk1, uint32_t one)
{
    const int s = blockIdx.x;
    const int h = blockIdx.y;
    const int t = threadIdx.x;
    __shared__ float Ws[5 * D_H];
    __shared__ float bsm[5];

#pragma unroll
    for (int i = 0; i < (5 * D_H) / 256; i++) {
        int j = t + 256 * i;
        uint32_t e = (uint32_t)(s * (D_OUT * D_H) + h * (5 * D_H) + j);
        uint2 r = threefry2x32_dev(wk0, wk1, 0u, e, one);
        int jg = h * (5 * D_H) + j;
        Ws[j] = __fmaf_rn(__expf(vW[jg]), jax_normal_fast(r.x ^ r.y), muW[jg]);
    }
    if (t < 5) {
        int og = h * 5 + t;
        uint2 r = threefry2x32_dev(bk0, bk1, 0u, (uint32_t)(s * D_OUT + og), one);
        bsm[t] = __fmaf_rn(__expf(vb[og]), jax_normal_fast(r.x ^ r.y), mub[og]);
    }
    __syncthreads();

    const int w = t >> 5, l = t & 31;
#pragma unroll
    for (int ri = 0; ri < 8; ri++) {
        int b = w * 8 + ri;
        const float* Hb = H + ((long long)s * BATCH + b) * D_H;
        float hh[16];
#pragma unroll
        for (int i = 0; i < 16; i++) hh[i] = Hb[l + 32 * i];
#pragma unroll
        for (int o = 0; o < 5; o++) {
            float acc = 0.0f;
#pragma unroll
            for (int i = 0; i < 16; i++)
                acc = __fmaf_rn(hh[i], Ws[o * D_H + l + 32 * i], acc);
            acc += __shfl_xor_sync(0xffffffffu, acc, 16);
            acc += __shfl_xor_sync(0xffffffffu, acc, 8);
            acc += __shfl_xor_sync(0xffffffffu, acc, 4);
            acc += __shfl_xor_sync(0xffffffffu, acc, 2);
            acc += __shfl_xor_sync(0xffffffffu, acc, 1);
            if (l == 0)
                out[((long long)s * BATCH + b) * D_OUT + h * 5 + o] = acc + bsm[o];
        }
    }
}

// ---------------- host-side threefry (subkey derivation) ----------------
static inline uint32_t h_rotl(uint32_t x, int r) { return (x << r) | (x >> (32 - r)); }
static void tf_host(uint32_t k0, uint32_t k1, uint32_t x0, uint32_t x1,
                    uint32_t* o0, uint32_t* o1) {
    uint32_t k2 = k0 ^ k1 ^ 0x1BD11BDAu;
    x0 += k0; x1 += k1;
    static const int R[2][4] = {{13,15,26,6},{17,29,16,24}};
    const uint32_t ks[3] = {k0, k1, k2};
    for (int i = 0; i < 5; i++) {
        for (int r = 0; r < 4; r++) {
            x0 += x1; x1 = h_rotl(x1, R[i & 1][r]); x1 ^= x0;
        }
        x0 += ks[(i + 1) % 3];
        x1 += ks[(i + 2) % 3] + (uint32_t)(i + 1);
    }
    *o0 = x0; *o1 = x1;
}

extern "C" void kernel_launch(void* const* d_in, const int* in_sizes, int n_in,
                              void* d_out, int out_size) {
    const float* x    = (const float*)d_in[0];
    const float* muW0 = (const float*)d_in[1];
    const float* mub0 = (const float*)d_in[2];
    const float* muW1 = (const float*)d_in[3];
    const float* mub1 = (const float*)d_in[4];
    const float* muW2 = (const float*)d_in[5];
    const float* mub2 = (const float*)d_in[6];
    const float* muW3 = (const float*)d_in[7];
    const float* mub3 = (const float*)d_in[8];
    const float* vW0  = (const float*)d_in[9];
    const float* vb0  = (const float*)d_in[10];
    const float* vW1  = (const float*)d_in[11];
    const float* vb1  = (const float*)d_in[12];
    const float* vW2  = (const float*)d_in[13];
    const float* vb2  = (const float*)d_in[14];
    const float* vW3  = (const float*)d_in[15];
    const float* vb3  = (const float*)d_in[16];
    float* out = (float*)d_out;

    uint32_t kk[8][2];
    for (int i = 0; i < 8; i++) tf_host(0u, 1u, 0u, (uint32_t)i, &kk[i][0], &kk[i][1]);

    float *pX, *pH1, *pH2, *pH3, *pSd0, *pSd1, *pSd2;
    cudaGetSymbolAddress((void**)&pX,   g_X);
    cudaGetSymbolAddress((void**)&pH1,  g_H1);
    cudaGetSymbolAddress((void**)&pH2,  g_H2);
    cudaGetSymbolAddress((void**)&pH3,  g_H3);
    cudaGetSymbolAddress((void**)&pSd0, g_sd0);
    cudaGetSymbolAddress((void**)&pSd1, g_sd1);
    cudaGetSymbolAddress((void**)&pSd2, g_sd2);

    const uint32_t one = 1u;   // runtime constant -> forces IMAD in threefry rounds

    prep_all<<<(NV0 + 255) / 256, 256>>>(x, vW0, vW1, vW2, pX, pSd0, pSd1, pSd2);

    fused_layer<<<dim3(D_H/64, NSAMP), 256>>>(pX,  0,
                                              muW0, pSd0, mub0, vb0,
                                              pH1, D_IN, D_H, 1, 1,
                                              kk[0][0], kk[0][1], kk[1][0], kk[1][1], one);
    fused_layer<<<dim3(D_H/64, NSAMP), 256>>>(pH1, (long long)BATCH*D_H,
                                              muW1, pSd1, mub1, vb1,
                                              pH2, D_H, D_H, 1, 1,
                                              kk[2][0], kk[2][1], kk[3][0], kk[3][1], one);
    fused_layer<<<dim3(D_H/64, NSAMP), 256>>>(pH2, (long long)BATCH*D_H,
                                              muW2, pSd2, mub2, vb2,
                                              pH3, D_H, D_H, 1, 0,
                                              kk[4][0], kk[4][1], kk[5][0], kk[5][1], one);
    layer3_fused<<<dim3(NSAMP, 2), 256>>>(pH3, muW3, vW3, mub3, vb3, out,
                                          kk[6][0], kk[6][1], kk[7][0], kk[7][1], one);
}

// round 17
// speedup vs baseline: 1.2151x; 1.0032x over previous
#include <cuda_runtime.h>
#include <stdint.h>

#define NSAMP 150
#define D_IN  784
#define D_H   512
#define D_OUT 10
#define BATCH 64

// ---------------- device scratch ----------------
__device__ __align__(16) float g_X  [BATCH * D_IN];          // tf32-rounded x
__device__ __align__(16) float g_H1 [NSAMP * BATCH * D_H];   // tf32-rounded
__device__ __align__(16) float g_H2 [NSAMP * BATCH * D_H];   // tf32-rounded
__device__ __align__(16) float g_H3 [NSAMP * BATCH * D_H];   // fp32 (layer3 input)
__device__ __align__(16) float g_sd0[D_H * D_IN];            // sqrt2*exp(vW0)
__device__ __align__(16) float g_sd1[D_H * D_H];             // sqrt2*exp(vW1)
__device__ __align__(16) float g_sd2[D_H * D_H];             // sqrt2*exp(vW2)

// ---------------- tf32 helpers ----------------
__device__ __forceinline__ float tf32_round(float a) {
    uint32_t h;
    asm("cvt.rna.tf32.f32 %0, %1;" : "=r"(h) : "f"(a));
    return __uint_as_float(h);
}
__device__ __forceinline__ void mma_tf32(float* c,
                                         uint32_t a0, uint32_t a1, uint32_t a2, uint32_t a3,
                                         uint32_t b0, uint32_t b1) {
    asm("mma.sync.aligned.m16n8k8.row.col.f32.tf32.tf32.f32 "
        "{%0,%1,%2,%3}, {%4,%5,%6,%7}, {%8,%9}, {%0,%1,%2,%3};"
        : "+f"(c[0]), "+f"(c[1]), "+f"(c[2]), "+f"(c[3])
        : "r"(a0), "r"(a1), "r"(a2), "r"(a3), "r"(b0), "r"(b1));
}

// ---------------- threefry2x32 (20 rounds), bit-exact vs jax._src.prng ----------------
// Entry folded: counter x0 == 0 always => post-keyadd x0 = k0 (no op); caller passes
// x1pre = counter + k1 (hoisted). Round adds on FMA pipe via IMAD (runtime 'one').
__device__ __forceinline__ void imad_add(uint32_t& d, uint32_t a, uint32_t one) {
    asm("mad.lo.u32 %0, %1, %2, %0;" : "+r"(d) : "r"(a), "r"(one));
}
__device__ __forceinline__ void tf_round_m(uint32_t& x0, uint32_t& x1, int r, uint32_t one) {
    imad_add(x0, x1, one);                 // x0 += x1   (IMAD, fma pipe)
    x1 = __funnelshift_l(x1, x1, r);       // SHF        (alu pipe)
    x1 ^= x0;                              // LOP3       (alu pipe)
}
__device__ __forceinline__ uint2 threefry2x32_pre(uint32_t k0, uint32_t k1,
                                                  uint32_t x1pre, uint32_t one) {
    uint32_t k2 = k0 ^ k1 ^ 0x1BD11BDAu;
    uint32_t x0 = k0;                      // = 0 + k0
    uint32_t x1 = x1pre;                   // = counter + k1
    tf_round_m(x0,x1,13,one); tf_round_m(x0,x1,15,one); tf_round_m(x0,x1,26,one); tf_round_m(x0,x1,6,one);
    imad_add(x0, k1, one); x1 += k2 + 1u;
    tf_round_m(x0,x1,17,one); tf_round_m(x0,x1,29,one); tf_round_m(x0,x1,16,one); tf_round_m(x0,x1,24,one);
    imad_add(x0, k2, one); x1 += k0 + 2u;
    tf_round_m(x0,x1,13,one); tf_round_m(x0,x1,15,one); tf_round_m(x0,x1,26,one); tf_round_m(x0,x1,6,one);
    imad_add(x0, k0, one); x1 += k1 + 3u;
    tf_round_m(x0,x1,17,one); tf_round_m(x0,x1,29,one); tf_round_m(x0,x1,16,one); tf_round_m(x0,x1,24,one);
    imad_add(x0, k1, one); x1 += k2 + 4u;
    tf_round_m(x0,x1,13,one); tf_round_m(x0,x1,15,one); tf_round_m(x0,x1,26,one); tf_round_m(x0,x1,6,one);
    imad_add(x0, k2, one); x1 += k0 + 5u;
    return make_uint2(x0, x1);
}

// ---------------- bits -> erfinv(u)  (p*x; sqrt2 folded into sd at prep) ----------------
// log done in base-2 (MUFU.LG2 raw); ln2 scaling fused into the poly shift.
__device__ __forceinline__ float erfinv_px(uint32_t bits) {
    const float LO = -0.99999994039535522461f;
    float f = __uint_as_float((bits >> 9) | 0x3f800000u) - 1.0f;
    float x = __fmaf_rn(f, 2.0f, LO);
    float t = __fmaf_rn(-x, x, 1.0f);
    float L = __log2f(t);                              // w = -ln2 * L
    float p;
    if (L > -7.2134752044448170f) {                    // w < 5
        float ww = __fmaf_rn(L, -0.69314718055994531f, -2.5f);
        p =                2.81022636e-08f;
        p = __fmaf_rn(p, ww, 3.43273939e-07f);
        p = __fmaf_rn(p, ww, -3.5233877e-06f);
        p = __fmaf_rn(p, ww, -4.39150654e-06f);
        p = __fmaf_rn(p, ww, 0.00021858087f);
        p = __fmaf_rn(p, ww, -0.00125372503f);
        p = __fmaf_rn(p, ww, -0.00417768164f);
        p = __fmaf_rn(p, ww, 0.246640727f);
        p = __fmaf_rn(p, ww, 1.50140941f);
    } else {
        float w  = L * -0.69314718055994531f;
        float ww = __fsqrt_rn(w) - 3.0f;
        p =                -0.000200214257f;
        p = __fmaf_rn(p, ww, 0.000100950558f);
        p = __fmaf_rn(p, ww, 0.00134934322f);
        p = __fmaf_rn(p, ww, -0.00367342844f);
        p = __fmaf_rn(p, ww, 0.00573950773f);
        p = __fmaf_rn(p, ww, -0.0076224613f);
        p = __fmaf_rn(p, ww, 0.00943887047f);
        p = __fmaf_rn(p, ww, 1.00167406f);
        p = __fmaf_rn(p, ww, 2.83297682f);
    }
    return p * x;
}
__device__ __forceinline__ float jax_normal_full(uint32_t bits) {
    return 1.4142135623730951f * erfinv_px(bits);
}

// gen 4 weights at k = kk..kk+3 (row n_glob), tf32-rounded. sd pre-scaled by sqrt2.
// eB1 = eBase + wk1 (hoisted key add).
__device__ __forceinline__ void gen_w4(const float* __restrict__ muRow,
                                       const float* __restrict__ sdRow,
                                       int kk, uint32_t eB1,
                                       uint32_t wk0, uint32_t wk1, uint32_t one,
                                       float* w) {
    float4 mv = *(const float4*)(muRow + kk);
    float4 sv = *(const float4*)(sdRow + kk);
    uint32_t ex = eB1 + (uint32_t)kk;
    uint2 r0 = threefry2x32_pre(wk0, wk1, ex + 0, one);
    uint2 r1 = threefry2x32_pre(wk0, wk1, ex + 1, one);
    uint2 r2 = threefry2x32_pre(wk0, wk1, ex + 2, one);
    uint2 r3 = threefry2x32_pre(wk0, wk1, ex + 3, one);
    w[0] = tf32_round(__fmaf_rn(sv.x, erfinv_px(r0.x ^ r0.y), mv.x));
    w[1] = tf32_round(__fmaf_rn(sv.y, erfinv_px(r1.x ^ r1.y), mv.y));
    w[2] = tf32_round(__fmaf_rn(sv.z, erfinv_px(r2.x ^ r2.y), mv.z));
    w[3] = tf32_round(__fmaf_rn(sv.w, erfinv_px(r3.x ^ r3.y), mv.w));
}

// gen stage (32 k) directly into smem buffers (no register staging)
__device__ __forceinline__ void gen_stage(
    const float* __restrict__ Ab, const float* __restrict__ muRow,
    const float* __restrict__ sdRow, int K, int k0,
    uint32_t eB1, uint32_t wk0, uint32_t wk1, uint32_t one,
    float (*Asb)[68], float (*Bsb)[68], int lr, int lk4)
{
    float4 av0 = *(const float4*)(Ab + (long long)lr * K + k0 + lk4);
    float w[4];
    gen_w4(muRow, sdRow, k0 + lk4, eB1, wk0, wk1, one, w);
    Asb[lk4+0][lr] = av0.x; Asb[lk4+1][lr] = av0.y;
    Asb[lk4+2][lr] = av0.z; Asb[lk4+3][lr] = av0.w;
    Bsb[lk4+0][lr] = w[0];  Bsb[lk4+1][lr] = w[1];
    Bsb[lk4+2][lr] = w[2];  Bsb[lk4+3][lr] = w[3];
    if (k0 + 32 <= K) {
        float4 av1 = *(const float4*)(Ab + (long long)lr * K + k0 + 16 + lk4);
        gen_w4(muRow, sdRow, k0 + 16 + lk4, eB1, wk0, wk1, one, w);
        Asb[16+lk4+0][lr] = av1.x; Asb[16+lk4+1][lr] = av1.y;
        Asb[16+lk4+2][lr] = av1.z; Asb[16+lk4+3][lr] = av1.w;
        Bsb[16+lk4+0][lr] = w[0];  Bsb[16+lk4+1][lr] = w[1];
        Bsb[16+lk4+2][lr] = w[2];  Bsb[16+lk4+3][lr] = w[3];
    } else {
        Asb[16+lk4+0][lr] = 0.f; Asb[16+lk4+1][lr] = 0.f;
        Asb[16+lk4+2][lr] = 0.f; Asb[16+lk4+3][lr] = 0.f;
        Bsb[16+lk4+0][lr] = 0.f; Bsb[16+lk4+1][lr] = 0.f;
        Bsb[16+lk4+2][lr] = 0.f; Bsb[16+lk4+3][lr] = 0.f;
    }
}

// ---------------- merged pre-kernel: round x + sqrt2*exp(vW0/vW1/vW2) ----------------
#define NX   (BATCH * D_IN)                    // 50176
#define NV0  (D_H * D_IN)                      // 401408
#define NV1  (D_H * D_H)                       // 262144
__global__ void prep_all(const float* __restrict__ x,
                         const float* __restrict__ vW0,
                         const float* __restrict__ vW1,
                         const float* __restrict__ vW2,
                         float* __restrict__ xr,
                         float* __restrict__ sd0,
                         float* __restrict__ sd1,
                         float* __restrict__ sd2) {
    int i = blockIdx.x * blockDim.x + threadIdx.x;
    const float S2 = 1.4142135623730951f;
    if (i < NX)  xr[i]  = tf32_round(x[i]);
    if (i < NV0) sd0[i] = S2 * __expf(vW0[i]);
    if (i < NV1) {
        sd1[i] = S2 * __expf(vW1[i]);
        sd2[i] = S2 * __expf(vW2[i]);
    }
}

// ---------------- fused layer: 64x64 tile, 32k stages, 1 barrier/stage, 1-term tf32 -------
__global__ __launch_bounds__(256, 4) void fused_layer(
    const float* __restrict__ A, long long strideA,
    const float* __restrict__ muW, const float* __restrict__ sdW,
    const float* __restrict__ mub, const float* __restrict__ vb,
    float* __restrict__ C, int K, int N, int relu, int round_out,
    uint32_t wk0, uint32_t wk1, uint32_t bk0, uint32_t bk1, uint32_t one)
{
    const int s    = blockIdx.y;
    const int nblk = blockIdx.x;
    const int t    = threadIdx.x;      // 256

    __shared__ float As[2][32][68];    // [buf][k][m]  (tf32 values)
    __shared__ float Bs[2][32][68];    // [buf][k][n]  (tf32 values)
    __shared__ float bias_s[64];

    const int lr   = t >> 2;           // 0..63 row (A-row / W-row) producer
    const int lk4  = (t & 3) << 2;     // k offset 0,4,8,12 within 16-k half
    const int lane = t & 31;
    const int wrp  = t >> 5;           // 0..7
    const int m0   = (wrp & 3) * 16;
    const int n0b  = (wrp >> 2) * 32;
    const int ka   = lane & 3;
    const int ra   = lane >> 2;

    const float* Ab     = A + (long long)s * strideA;
    const int    n_glob = nblk * 64 + lr;
    const float* muRow  = muW + (long long)n_glob * K;
    const float* sdRow  = sdW + (long long)n_glob * K;
    const uint32_t eBase = ((uint32_t)s * (uint32_t)N + (uint32_t)n_glob) * (uint32_t)K;
    const uint32_t eB1   = eBase + wk1;          // hoisted first-round key add

    if (t < 64) {
        int nb = nblk * 64 + t;
        uint2 r = threefry2x32_pre(bk0, bk1, (uint32_t)(s * N + nb) + bk1, one);
        bias_s[t] = __fmaf_rn(__expf(vb[nb]), jax_normal_full(r.x ^ r.y), mub[nb]);
    }

    const int nst = (K + 31) >> 5;     // 32-k stages (last half-stage zero-padded)

    // ---- prologue: gen stage 0 straight into buf 0 ----
    gen_stage(Ab, muRow, sdRow, K, 0, eB1, wk0, wk1, one, As[0], Bs[0], lr, lk4);

    float acc[4][4];
#pragma unroll
    for (int i = 0; i < 4; i++)
#pragma unroll
        for (int j = 0; j < 4; j++) acc[i][j] = 0.0f;

    // ---- main loop: sync | gen(c+1)->buf^1 | MMA(c) from buf ----
    for (int c = 0; c < nst; c++) {
        __syncthreads();
        const int buf = c & 1;

        if (c + 1 < nst) {
            gen_stage(Ab, muRow, sdRow, K, (c + 1) << 5, eB1, wk0, wk1, one,
                      As[buf ^ 1], Bs[buf ^ 1], lr, lk4);
        }

        // MMA over stage c: 4 k8-steps x 4 n8-tiles, 1-term (A & B both tf32)
#pragma unroll
        for (int ks = 0; ks < 4; ks++) {
            const int kb = ks * 8;
            uint32_t a0 = __float_as_uint(As[buf][kb + ka    ][m0 + ra    ]);
            uint32_t a1 = __float_as_uint(As[buf][kb + ka    ][m0 + ra + 8]);
            uint32_t a2 = __float_as_uint(As[buf][kb + ka + 4][m0 + ra    ]);
            uint32_t a3 = __float_as_uint(As[buf][kb + ka + 4][m0 + ra + 8]);
#pragma unroll
            for (int tj = 0; tj < 4; tj++) {
                uint32_t b0 = __float_as_uint(Bs[buf][kb + ka    ][n0b + tj * 8 + ra]);
                uint32_t b1 = __float_as_uint(Bs[buf][kb + ka + 4][n0b + tj * 8 + ra]);
                mma_tf32(acc[tj], a0, a1, a2, a3, b0, b1);
            }
        }
    }

    // ---- epilogue: +bias, relu, optional tf32 round, store ----
    const int row0 = m0 + ra;
    const int row1 = m0 + ra + 8;
#pragma unroll
    for (int tj = 0; tj < 4; tj++) {
        int n = n0b + tj * 8 + 2 * ka;
        float bb0 = bias_s[n], bb1 = bias_s[n + 1];
        float v00 = acc[tj][0] + bb0, v01 = acc[tj][1] + bb1;
        float v10 = acc[tj][2] + bb0, v11 = acc[tj][3] + bb1;
        if (relu) {
            v00 = fmaxf(v00, 0.f); v01 = fmaxf(v01, 0.f);
            v10 = fmaxf(v10, 0.f); v11 = fmaxf(v11, 0.f);
        }
        if (round_out) {
            v00 = tf32_round(v00); v01 = tf32_round(v01);
            v10 = tf32_round(v10); v11 = tf32_round(v11);
        }
        float* p0 = C + ((long long)s * 64 + row0) * N + nblk * 64 + n;
        float* p1 = C + ((long long)s * 64 + row1) * N + nblk * 64 + n;
        *(float2*)p0 = make_float2(v00, v01);
        *(float2*)p1 = make_float2(v10, v11);
    }
}

// ---------------- final layer: 2 blocks per sample, gen partitioned by output-half --------
__global__ __launch_bounds__(256) void layer3_fused(
    const float* __restrict__ H,
    const float* __restrict__ muW, const float* __restrict__ vW,
    const float* __restrict__ mub, const float* __restrict__ vb,
    float* __restrict__ out,
    uint32_t wk0, uint32_t wk1, uint32_t bk0, uint32_t bk1, uint32_t one)
{
    const int s = blockIdx.x;
    const int h = blockIdx.y;
    const int t = threadIdx.x;
    __shared__ float Ws[5 * D_H];
    __shared__ float bsm[5];

#pragma unroll
    for (int i = 0; i < (5 * D_H) / 256; i++) {
        int j = t + 256 * i;
        uint32_t e = (uint32_t)(s * (D_OUT * D_H) + h * (5 * D_H) + j);
        uint2 r = threefry2x32_pre(wk0, wk1, e + wk1, one);
        int jg = h * (5 * D_H) + j;
        Ws[j] = __fmaf_rn(__expf(vW[jg]), jax_normal_full(r.x ^ r.y), muW[jg]);
    }
    if (t < 5) {
        int og = h * 5 + t;
        uint2 r = threefry2x32_pre(bk0, bk1, (uint32_t)(s * D_OUT + og) + bk1, one);
        bsm[t] = __fmaf_rn(__expf(vb[og]), jax_normal_full(r.x ^ r.y), mub[og]);
    }
    __syncthreads();

    const int w = t >> 5, l = t & 31;
#pragma unroll
    for (int ri = 0; ri < 8; ri++) {
        int b = w * 8 + ri;
        const float* Hb = H + ((long long)s * BATCH + b) * D_H;
        float hh[16];
#pragma unroll
        for (int i = 0; i < 16; i++) hh[i] = Hb[l + 32 * i];
#pragma unroll
        for (int o = 0; o < 5; o++) {
            float acc = 0.0f;
#pragma unroll
            for (int i = 0; i < 16; i++)
                acc = __fmaf_rn(hh[i], Ws[o * D_H + l + 32 * i], acc);
            acc += __shfl_xor_sync(0xffffffffu, acc, 16);
            acc += __shfl_xor_sync(0xffffffffu, acc, 8);
            acc += __shfl_xor_sync(0xffffffffu, acc, 4);
            acc += __shfl_xor_sync(0xffffffffu, acc, 2);
            acc += __shfl_xor_sync(0xffffffffu, acc, 1);
            if (l == 0)
                out[((long long)s * BATCH + b) * D_OUT + h * 5 + o] = acc + bsm[o];
        }
    }
}

// ---------------- host-side threefry (subkey derivation) ----------------
static inline uint32_t h_rotl(uint32_t x, int r) { return (x << r) | (x >> (32 - r)); }
static void tf_host(uint32_t k0, uint32_t k1, uint32_t x0, uint32_t x1,
                    uint32_t* o0, uint32_t* o1) {
    uint32_t k2 = k0 ^ k1 ^ 0x1BD11BDAu;
    x0 += k0; x1 += k1;
    static const int R[2][4] = {{13,15,26,6},{17,29,16,24}};
    const uint32_t ks[3] = {k0, k1, k2};
    for (int i = 0; i < 5; i++) {
        for (int r = 0; r < 4; r++) {
            x0 += x1; x1 = h_rotl(x1, R[i & 1][r]); x1 ^= x0;
        }
        x0 += ks[(i + 1) % 3];
        x1 += ks[(i + 2) % 3] + (uint32_t)(i + 1);
    }
    *o0 = x0; *o1 = x1;
}

extern "C" void kernel_launch(void* const* d_in, const int* in_sizes, int n_in,
                              void* d_out, int out_size) {
    const float* x    = (const float*)d_in[0];
    const float* muW0 = (const float*)d_in[1];
    const float* mub0 = (const float*)d_in[2];
    const float* muW1 = (const float*)d_in[3];
    const float* mub1 = (const float*)d_in[4];
    const float* muW2 = (const float*)d_in[5];
    const float* mub2 = (const float*)d_in[6];
    const float* muW3 = (const float*)d_in[7];
    const float* mub3 = (const float*)d_in[8];
    const float* vW0  = (const float*)d_in[9];
    const float* vb0  = (const float*)d_in[10];
    const float* vW1  = (const float*)d_in[11];
    const float* vb1  = (const float*)d_in[12];
    const float* vW2  = (const float*)d_in[13];
    const float* vb2  = (const float*)d_in[14];
    const float* vW3  = (const float*)d_in[15];
    const float* vb3  = (const float*)d_in[16];
    float* out = (float*)d_out;

    uint32_t kk[8][2];
    for (int i = 0; i < 8; i++) tf_host(0u, 1u, 0u, (uint32_t)i, &kk[i][0], &kk[i][1]);

    float *pX, *pH1, *pH2, *pH3, *pSd0, *pSd1, *pSd2;
    cudaGetSymbolAddress((void**)&pX,   g_X);
    cudaGetSymbolAddress((void**)&pH1,  g_H1);
    cudaGetSymbolAddress((void**)&pH2,  g_H2);
    cudaGetSymbolAddress((void**)&pH3,  g_H3);
    cudaGetSymbolAddress((void**)&pSd0, g_sd0);
    cudaGetSymbolAddress((void**)&pSd1, g_sd1);
    cudaGetSymbolAddress((void**)&pSd2, g_sd2);

    const uint32_t one = 1u;   // runtime constant -> forces IMAD in threefry rounds

    prep_all<<<(NV0 + 255) / 256, 256>>>(x, vW0, vW1, vW2, pX, pSd0, pSd1, pSd2);

    fused_layer<<<dim3(D_H/64, NSAMP), 256>>>(pX,  0,
                                              muW0, pSd0, mub0, vb0,
                                              pH1, D_IN, D_H, 1, 1,
                                              kk[0][0], kk[0][1], kk[1][0], kk[1][1], one);
    fused_layer<<<dim3(D_H/64, NSAMP), 256>>>(pH1, (long long)BATCH*D_H,
                                              muW1, pSd1, mub1, vb1,
                                              pH2, D_H, D_H, 1, 1,
                                              kk[2][0], kk[2][1], kk[3][0], kk[3][1], one);
    fused_layer<<<dim3(D_H/64, NSAMP), 256>>>(pH2, (long long)BATCH*D_H,
                                              muW2, pSd2, mub2, vb2,
                                              pH3, D_H, D_H, 1, 0,
                                              kk[4][0], kk[4][1], kk[5][0], kk[5][1], one);
    layer3_fused<<<dim3(NSAMP, 2), 256>>>(pH3, muW3, vW3, mub3, vb3, out,
                                          kk[6][0], kk[6][1], kk[7][0], kk[7][1], one);
}